// round 12
// baseline (speedup 1.0000x reference)
#include <cuda_runtime.h>
#include <cstdint>

#define B_      8
#define SEQ     1024
#define DMODEL  768
#define NHEADS  12
#define HDIM    64

// Scratch (allocation-free: __device__ globals)
__device__ float g_q  [B_*SEQ*DMODEL];            // 25 MB
__device__ float g_kv [B_*SEQ*2*DMODEL];          // 50 MB
__device__ float g_ctx[B_*SEQ*DMODEL];            // 25 MB
__device__ float g_vt [B_*NHEADS*HDIM*SEQ];       // 25 MB  V^T per (b,h): [64][1024]

// ---------------------------------------------------------------------------
// helpers
// ---------------------------------------------------------------------------
__device__ __forceinline__ uint32_t smem_u32(const void* p) {
    uint32_t a;
    asm("{ .reg .u64 t; cvta.to.shared.u64 t, %1; cvt.u32.u64 %0, t; }"
        : "=r"(a) : "l"(p));
    return a;
}

// cvt.rn.bf16x2.f32 d, hi, lo  ->  d.lo = bf16(lo-arg), d.hi = bf16(hi-arg)
__device__ __forceinline__ uint32_t pack_bf2(float a, float b) {
    uint32_t r;
    asm("cvt.rn.bf16x2.f32 %0, %1, %2;" : "=r"(r) : "f"(b), "f"(a));
    return r;
}

// 8 fp32 -> 8 bf16 hi + 8 bf16 residual lo
__device__ __forceinline__ void cvt8(float4 f0, float4 f1, uint4& hv, uint4& lv) {
    uint32_t h0 = pack_bf2(f0.x, f0.y);
    uint32_t h1 = pack_bf2(f0.z, f0.w);
    uint32_t h2 = pack_bf2(f1.x, f1.y);
    uint32_t h3 = pack_bf2(f1.z, f1.w);
    hv = make_uint4(h0, h1, h2, h3);
    float r0 = f0.x - __uint_as_float(h0 << 16);
    float r1 = f0.y - __uint_as_float(h0 & 0xffff0000u);
    float r2 = f0.z - __uint_as_float(h1 << 16);
    float r3 = f0.w - __uint_as_float(h1 & 0xffff0000u);
    float r4 = f1.x - __uint_as_float(h2 << 16);
    float r5 = f1.y - __uint_as_float(h2 & 0xffff0000u);
    float r6 = f1.z - __uint_as_float(h3 << 16);
    float r7 = f1.w - __uint_as_float(h3 & 0xffff0000u);
    lv = make_uint4(pack_bf2(r0, r1), pack_bf2(r2, r3),
                    pack_bf2(r4, r5), pack_bf2(r6, r7));
}

__device__ __forceinline__ void ldsm4(uint32_t addr, uint32_t* r) {
    asm volatile("ldmatrix.sync.aligned.m8n8.x4.shared.b16 {%0,%1,%2,%3}, [%4];"
        : "=r"(r[0]), "=r"(r[1]), "=r"(r[2]), "=r"(r[3]) : "r"(addr));
}

__device__ __forceinline__ void mma16816(float* d, const uint32_t* a, const uint32_t* b) {
    asm volatile(
        "mma.sync.aligned.m16n8k16.row.col.f32.bf16.bf16.f32 "
        "{%0,%1,%2,%3},{%4,%5,%6,%7},{%8,%9},{%0,%1,%2,%3};"
        : "+f"(d[0]), "+f"(d[1]), "+f"(d[2]), "+f"(d[3])
        : "r"(a[0]), "r"(a[1]), "r"(a[2]), "r"(a[3]), "r"(b[0]), "r"(b[1]));
}

// ---------------------------------------------------------------------------
// HMMA GEMM: C[128,64] = alpha * (A @ B^T) (+bias).
// A:[M,K] fp32 row-major (lda), B:[N,K] fp32 row-major (ldb).
// fp32 -> bf16-pair on smem fill; 3 MMAs (hh, hl, lh) per m16n8k16 tile.
// K multiple of 32. 256 threads, >=2 CTAs/SM. Warp grid 4(m) x 2(n),
// warp tile 32x32. smem rows 64 B = 4 x 16B chunks, swizzle chunk ^ (row&3).
// ---------------------------------------------------------------------------
__global__ void __launch_bounds__(256, 2)
gemm_hmma(const float* __restrict__ A, const float* __restrict__ Bm,
          float* __restrict__ C, const float* __restrict__ bias,
          int K, int lda, int ldb, int ldc,
          int zdiv,
          long long sAo, long long sAi,
          long long sBo, long long sBi,
          long long sCo, long long sCi,
          float alpha)
{
    extern __shared__ char smem[];
    const int ASZ = 128 * 64;          // A bf16 tile bytes (128 rows x 64 B)
    const int BSZ = 64 * 64;           // B bf16 tile bytes
    const int STG = 2 * ASZ + 2 * BSZ; // AH | AL | BH | BL = 24 KB
    const int NT  = 4;                 // n8 tiles per warp (32 cols)

    int z  = blockIdx.z;
    int zo = z / zdiv, zi = z - zo * zdiv;
    A  += zo * sAo + zi * sAi;
    Bm += zo * sBo + zi * sBi;
    C  += zo * sCo + zi * sCi;

    int t    = threadIdx.x;
    int warp = t >> 5, lane = t & 31;
    int wm   = warp >> 1, wn = warp & 1;

    int row0 = blockIdx.y << 7;
    int col0 = blockIdx.x << 6;

    // fill roles:
    //   A: thread t -> row t>>1, chunks (t&1)*2 .. +1  (16 floats)
    //   B: thread t -> row t>>2, chunk  t&3            (8 floats)
    int frA = t >> 1, fcA = (t & 1) << 1;
    int frB = t >> 2, fcB = t & 3;
    uint32_t offA0 = (uint32_t)frA * 64 + (((fcA + 0) ^ (frA & 3)) << 4);
    uint32_t offA1 = (uint32_t)frA * 64 + (((fcA + 1) ^ (frA & 3)) << 4);
    uint32_t offB  = (uint32_t)frB * 64 + ((fcB ^ (frB & 3)) << 4);
    const float* Asrc = A + (long long)(row0 + frA) * lda + fcA * 8;
    const float* Bsrc = Bm + (long long)(col0 + frB) * ldb + fcB * 8;

    uint32_t sb = smem_u32(smem);

    float acc[2][NT][4];
    #pragma unroll
    for (int i = 0; i < 2; i++)
        #pragma unroll
        for (int j = 0; j < NT; j++)
            #pragma unroll
            for (int q = 0; q < 4; q++) acc[i][j][q] = 0.0f;

    int nk = K >> 5;

    // prologue: fill stage 0
    {
        float4 a0 = *(const float4*)(Asrc);
        float4 a1 = *(const float4*)(Asrc + 4);
        float4 a2 = *(const float4*)(Asrc + 8);
        float4 a3 = *(const float4*)(Asrc + 12);
        float4 b0 = *(const float4*)(Bsrc);
        float4 b1 = *(const float4*)(Bsrc + 4);
        uint4 hv, lv;
        cvt8(a0, a1, hv, lv);
        *(uint4*)(smem + offA0)       = hv;
        *(uint4*)(smem + ASZ + offA0) = lv;
        cvt8(a2, a3, hv, lv);
        *(uint4*)(smem + offA1)       = hv;
        *(uint4*)(smem + ASZ + offA1) = lv;
        cvt8(b0, b1, hv, lv);
        *(uint4*)(smem + 2 * ASZ + offB)       = hv;
        *(uint4*)(smem + 2 * ASZ + BSZ + offB) = lv;
    }
    __syncthreads();

    // ldmatrix address components (verified mapping from R9, resized)
    int arow_base = wm * 32 + (lane & 15);                      // + mi*16
    int asel      = lane >> 4;                                  // k-chunk half
    int nrow_base = wn * 32 + (lane & 7) + ((lane >> 4) << 3);  // + p*16
    int bsel      = (lane >> 3) & 1;

    for (int it = 0; it < nk; it++) {
        int cur = it & 1;
        bool more = (it + 1 < nk);
        float4 la0, la1, la2, la3, lb0, lb1;
        if (more) {
            int k0 = (it + 1) << 5;
            la0 = *(const float4*)(Asrc + k0);
            la1 = *(const float4*)(Asrc + k0 + 4);
            la2 = *(const float4*)(Asrc + k0 + 8);
            la3 = *(const float4*)(Asrc + k0 + 12);
            lb0 = *(const float4*)(Bsrc + k0);
            lb1 = *(const float4*)(Bsrc + k0 + 4);
        }

        uint32_t sA = sb + cur * STG;
        uint32_t sB = sA + 2 * ASZ;

        #pragma unroll
        for (int ks = 0; ks < 2; ks++) {
            uint32_t ah[2][4], al[2][4];
            #pragma unroll
            for (int mi = 0; mi < 2; mi++) {
                int r = arow_base + mi * 16;
                uint32_t ch = (uint32_t)(ks * 2 + asel) ^ (r & 3);
                uint32_t off = (uint32_t)r * 64 + (ch << 4);
                ldsm4(sA + off, ah[mi]);
                ldsm4(sA + ASZ + off, al[mi]);
            }
            uint32_t bh[NT][2], bl[NT][2];
            #pragma unroll
            for (int p = 0; p < NT / 2; p++) {
                int n = nrow_base + p * 16;
                uint32_t ch = (uint32_t)(ks * 2 + bsel) ^ (n & 3);
                uint32_t off = (uint32_t)n * 64 + (ch << 4);
                uint32_t rh[4], rl[4];
                ldsm4(sB + off, rh);
                ldsm4(sB + BSZ + off, rl);
                bh[2 * p][0] = rh[0]; bh[2 * p][1] = rh[1];
                bh[2 * p + 1][0] = rh[2]; bh[2 * p + 1][1] = rh[3];
                bl[2 * p][0] = rl[0]; bl[2 * p][1] = rl[1];
                bl[2 * p + 1][0] = rl[2]; bl[2 * p + 1][1] = rl[3];
            }
            #pragma unroll
            for (int mi = 0; mi < 2; mi++)
                #pragma unroll
                for (int ni = 0; ni < NT; ni++) {
                    mma16816(acc[mi][ni], ah[mi], bh[ni]);
                    mma16816(acc[mi][ni], ah[mi], bl[ni]);
                    mma16816(acc[mi][ni], al[mi], bh[ni]);
                }
        }

        if (more) {
            int nxt = cur ^ 1;
            char* st = smem + nxt * STG;
            uint4 hv, lv;
            cvt8(la0, la1, hv, lv);
            *(uint4*)(st + offA0)       = hv;
            *(uint4*)(st + ASZ + offA0) = lv;
            cvt8(la2, la3, hv, lv);
            *(uint4*)(st + offA1)       = hv;
            *(uint4*)(st + ASZ + offA1) = lv;
            cvt8(lb0, lb1, hv, lv);
            *(uint4*)(st + 2 * ASZ + offB)       = hv;
            *(uint4*)(st + 2 * ASZ + BSZ + offB) = lv;
        }
        __syncthreads();
    }

    // epilogue: c0,c1 -> (row, col..col+1); c2,c3 -> (row+8, same cols)
    #pragma unroll
    for (int mi = 0; mi < 2; mi++) {
        int r = row0 + wm * 32 + mi * 16 + (lane >> 2);
        #pragma unroll
        for (int ni = 0; ni < NT; ni++) {
            int cidx = col0 + wn * 32 + ni * 8 + (lane & 3) * 2;
            float b0 = 0.f, b1 = 0.f;
            if (bias) { b0 = bias[cidx]; b1 = bias[cidx + 1]; }
            float* cp = C + (long long)r * ldc + cidx;
            *(float2*)cp = make_float2(acc[mi][ni][0] * alpha + b0,
                                       acc[mi][ni][1] * alpha + b1);
            cp += 8 * ldc;
            *(float2*)cp = make_float2(acc[mi][ni][2] * alpha + b0,
                                       acc[mi][ni][3] * alpha + b1);
        }
    }
}

// ---------------------------------------------------------------------------
// Transpose V half of kv into g_vt[(b*12+h)*64 + d][tok]  (64x64 smem tiles)
// ---------------------------------------------------------------------------
__global__ void __launch_bounds__(256)
transpose_v(const float* __restrict__ kv, float* __restrict__ vt)
{
    __shared__ float s[64][65];
    int bh = blockIdx.x;
    int b = bh / NHEADS, h = bh - b * NHEADS;
    int tk = blockIdx.y << 6;
    int t = threadIdx.x;
    int tl = t >> 2;             // 0..63
    int ds = (t & 3) << 4;       // 0,16,32,48

    const float* src = kv + ((long long)(b * SEQ + tk + tl)) * (2 * DMODEL)
                          + DMODEL + h * HDIM + ds;
    #pragma unroll
    for (int j = 0; j < 16; j += 4) {
        float4 v = *(const float4*)(src + j);
        s[tl][ds + j + 0] = v.x; s[tl][ds + j + 1] = v.y;
        s[tl][ds + j + 2] = v.z; s[tl][ds + j + 3] = v.w;
    }
    __syncthreads();

    int dl = t >> 2;
    int ts = (t & 3) << 4;
    float* dst = vt + ((long long)(bh * HDIM + dl)) * SEQ + tk + ts;
    #pragma unroll
    for (int j = 0; j < 16; j += 4) {
        float4 v;
        v.x = s[ts + j + 0][dl]; v.y = s[ts + j + 1][dl];
        v.z = s[ts + j + 2][dl]; v.w = s[ts + j + 3][dl];
        *(float4*)(dst + j) = v;
    }
}

// ---------------------------------------------------------------------------
// In-place softmax over rows of 1024. One 256-thread block per row.
// ---------------------------------------------------------------------------
__global__ void softmax_rows(float* __restrict__ attn)
{
    float* p = attn + (long long)blockIdx.x * SEQ;
    int t = threadIdx.x;
    float4 v = ((float4*)p)[t];

    __shared__ float red[8];

    float m = fmaxf(fmaxf(v.x, v.y), fmaxf(v.z, v.w));
    #pragma unroll
    for (int o = 16; o > 0; o >>= 1)
        m = fmaxf(m, __shfl_xor_sync(0xffffffffu, m, o));
    if ((t & 31) == 0) red[t >> 5] = m;
    __syncthreads();
    float bm = red[0];
    #pragma unroll
    for (int i = 1; i < 8; i++) bm = fmaxf(bm, red[i]);

    float e0 = expf(v.x - bm), e1 = expf(v.y - bm);
    float e2 = expf(v.z - bm), e3 = expf(v.w - bm);
    float s = (e0 + e1) + (e2 + e3);
    #pragma unroll
    for (int o = 16; o > 0; o >>= 1)
        s += __shfl_xor_sync(0xffffffffu, s, o);
    __syncthreads();
    if ((t & 31) == 0) red[t >> 5] = s;
    __syncthreads();
    float bs = red[0];
    #pragma unroll
    for (int i = 1; i < 8; i++) bs += red[i];

    float inv = 1.0f / bs;
    ((float4*)p)[t] = make_float4(e0 * inv, e1 * inv, e2 * inv, e3 * inv);
}

// ---------------------------------------------------------------------------
// d_in: 0=x [8,1024,768] f32, 1=q_w [768,768], 2=kv_w [1536,768],
//       3=proj_w [768,768], 4=proj_b [768], 5=H, 6=W
// d_out: out [8*1024*768] f32 followed by attn [8*12*1024*1024] f32
// ---------------------------------------------------------------------------
extern "C" void kernel_launch(void* const* d_in, const int* in_sizes, int n_in,
                              void* d_out, int out_size)
{
    const float* x   = (const float*)d_in[0];
    const float* qw  = (const float*)d_in[1];
    const float* kvw = (const float*)d_in[2];
    const float* pw  = (const float*)d_in[3];
    const float* pb  = (const float*)d_in[4];

    float* out  = (float*)d_out;
    float* attn = out + (long long)B_ * SEQ * DMODEL;

    float *gq, *gkv, *gctx, *gvt;
    cudaGetSymbolAddress((void**)&gq,   g_q);
    cudaGetSymbolAddress((void**)&gkv,  g_kv);
    cudaGetSymbolAddress((void**)&gctx, g_ctx);
    cudaGetSymbolAddress((void**)&gvt,  g_vt);

    // dynamic smem: 2 stages * (AH+AL+BH+BL) = 48 KB
    const int SMEM = 2 * (2 * 128 * 64 + 2 * 64 * 64);
    cudaFuncSetAttribute(gemm_hmma, cudaFuncAttributeMaxDynamicSharedMemorySize, SMEM);

    const int MROWS = B_ * SEQ;                 // 8192
    const long long SS = (long long)SEQ * SEQ;

    // 1) Q = x @ q_w^T           [8192, 768]
    gemm_hmma<<<dim3(DMODEL / 64, MROWS / 128, 1), 256, SMEM>>>(
        x, qw, gq, nullptr,
        DMODEL, DMODEL, DMODEL, DMODEL,
        1, 0, 0, 0, 0, 0, 0, 1.0f);

    // 2) KV = x @ kv_w^T         [8192, 1536]
    gemm_hmma<<<dim3(2 * DMODEL / 64, MROWS / 128, 1), 256, SMEM>>>(
        x, kvw, gkv, nullptr,
        DMODEL, DMODEL, DMODEL, 2 * DMODEL,
        1, 0, 0, 0, 0, 0, 0, 1.0f);

    // 2b) V^T per (b,h)
    transpose_v<<<dim3(B_ * NHEADS, SEQ / 64, 1), 256>>>(gkv, gvt);

    // 3) S[b,h] = 0.125 * Q_h @ K_h^T   (96 batched [1024,1024,64])
    gemm_hmma<<<dim3(SEQ / 64, SEQ / 128, B_ * NHEADS), 256, SMEM>>>(
        gq, gkv, attn, nullptr,
        HDIM, DMODEL, 2 * DMODEL, SEQ,
        NHEADS,
        (long long)SEQ * DMODEL,     HDIM,        // A: per-b, per-h
        (long long)SEQ * 2 * DMODEL, HDIM,        // B (K half of kv)
        (long long)NHEADS * SS,      SS,          // C
        0.125f);

    // 4) row softmax in place
    softmax_rows<<<B_ * NHEADS * SEQ, 256>>>(attn);

    // 5) ctx[b,:,h*64..] = attn[b,h] @ Vt[b,h]^T   (NT with B = V^T [64,1024])
    gemm_hmma<<<dim3(1, SEQ / 128, B_ * NHEADS), 256, SMEM>>>(
        attn, gvt, gctx, nullptr,
        SEQ, SEQ, SEQ, DMODEL,
        NHEADS,
        (long long)NHEADS * SS,          SS,                     // A
        (long long)NHEADS * HDIM * SEQ,  (long long)HDIM * SEQ,  // B
        (long long)SEQ * DMODEL,         HDIM,                   // C
        1.0f);

    // 6) out = ctx @ proj_w^T + proj_b
    gemm_hmma<<<dim3(DMODEL / 64, MROWS / 128, 1), 256, SMEM>>>(
        gctx, pw, out, pb,
        DMODEL, DMODEL, DMODEL, DMODEL,
        1, 0, 0, 0, 0, 0, 0, 1.0f);
}

// round 14
// speedup vs baseline: 1.1579x; 1.1579x over previous
#include <cuda_runtime.h>
#include <cuda_fp16.h>
#include <cstdint>

#define B_      8
#define SEQ     1024
#define DMODEL  768
#define NHEADS  12
#define HDIM    64

// Scratch (allocation-free: __device__ globals)
__device__ float g_q  [B_*SEQ*DMODEL];            // 25 MB
__device__ float g_kv [B_*SEQ*2*DMODEL];          // 50 MB
__device__ float g_ctx[B_*SEQ*DMODEL];            // 25 MB
__device__ float g_vt [B_*NHEADS*HDIM*SEQ];       // 25 MB  V^T per (b,h): [64][1024]

// ---------------------------------------------------------------------------
// helpers
// ---------------------------------------------------------------------------
__device__ __forceinline__ uint32_t smem_u32(const void* p) {
    uint32_t a;
    asm("{ .reg .u64 t; cvta.to.shared.u64 t, %1; cvt.u32.u64 %0, t; }"
        : "=r"(a) : "l"(p));
    return a;
}

__device__ __forceinline__ uint32_t packh2(float a, float b) {
    __half2 h = __floats2half2_rn(a, b);
    return *reinterpret_cast<uint32_t*>(&h);
}

// 8 fp32 -> 8 fp16 hi + 8 fp16 residual lo (A operand)
__device__ __forceinline__ void cvt8h(float4 f0, float4 f1, uint4& hv, uint4& lv) {
    uint32_t h0 = packh2(f0.x, f0.y);
    uint32_t h1 = packh2(f0.z, f0.w);
    uint32_t h2 = packh2(f1.x, f1.y);
    uint32_t h3 = packh2(f1.z, f1.w);
    hv = make_uint4(h0, h1, h2, h3);
    __half2 H0 = *(__half2*)&h0, H1 = *(__half2*)&h1;
    __half2 H2 = *(__half2*)&h2, H3 = *(__half2*)&h3;
    lv = make_uint4(
        packh2(f0.x - __low2float(H0), f0.y - __high2float(H0)),
        packh2(f0.z - __low2float(H1), f0.w - __high2float(H1)),
        packh2(f1.x - __low2float(H2), f1.y - __high2float(H2)),
        packh2(f1.z - __low2float(H3), f1.w - __high2float(H3)));
}

// 8 fp32 -> 8 fp16 (B operand, hi only)
__device__ __forceinline__ uint4 cvt8h_hi(float4 f0, float4 f1) {
    return make_uint4(packh2(f0.x, f0.y), packh2(f0.z, f0.w),
                      packh2(f1.x, f1.y), packh2(f1.z, f1.w));
}

__device__ __forceinline__ void ldsm4(uint32_t addr, uint32_t* r) {
    asm volatile("ldmatrix.sync.aligned.m8n8.x4.shared.b16 {%0,%1,%2,%3}, [%4];"
        : "=r"(r[0]), "=r"(r[1]), "=r"(r[2]), "=r"(r[3]) : "r"(addr));
}

__device__ __forceinline__ void mma16816(float* d, const uint32_t* a, const uint32_t* b) {
    asm volatile(
        "mma.sync.aligned.m16n8k16.row.col.f32.f16.f16.f32 "
        "{%0,%1,%2,%3},{%4,%5,%6,%7},{%8,%9},{%0,%1,%2,%3};"
        : "+f"(d[0]), "+f"(d[1]), "+f"(d[2]), "+f"(d[3])
        : "r"(a[0]), "r"(a[1]), "r"(a[2]), "r"(a[3]), "r"(b[0]), "r"(b[1]));
}

// ---------------------------------------------------------------------------
// HMMA GEMM: C[128,BN] = alpha * (A @ B^T) (+bias).
// A:[M,K] fp32 row-major (lda), B:[N,K] fp32 row-major (ldb).
// fp32 -> fp16 on smem fill. A split hi+lo, B hi only:
//   acc += A_hi*B_hi + A_lo*B_hi  = A*B_hi   (2 MMAs per m16n8k16 tile)
// K multiple of 32. 512 threads. BN in {64, 128}.
// smem rows: 32 fp16 = 64 B = 4 x 16B chunks, swizzle chunk ^ (row & 3).
// ---------------------------------------------------------------------------
template <int BN>
__global__ void __launch_bounds__(512)
gemm_hmma(const float* __restrict__ A, const float* __restrict__ Bm,
          float* __restrict__ C, const float* __restrict__ bias,
          int K, int lda, int ldb, int ldc,
          int zdiv,
          long long sAo, long long sAi,
          long long sBo, long long sBi,
          long long sCo, long long sCi,
          float alpha)
{
    extern __shared__ char smem[];
    const int ASZ = 128 * 64;          // A fp16 tile bytes (128 rows x 64 B)
    const int BSZ = BN * 64;
    const int STG = 2 * ASZ + BSZ;     // AH | AL | BH
    const int WN  = BN / 4;            // warp n-width: 32 or 16
    const int NT  = WN / 8;            // n8 tiles per warp: 4 or 2

    int z  = blockIdx.z;
    int zo = z / zdiv, zi = z - zo * zdiv;
    A  += zo * sAo + zi * sAi;
    Bm += zo * sBo + zi * sBi;
    C  += zo * sCo + zi * sCi;

    int t    = threadIdx.x;
    int warp = t >> 5, lane = t & 31;
    int wm   = warp >> 2, wn = warp & 3;

    int row0 = blockIdx.y << 7;
    int col0 = blockIdx.x * BN;

    // fill roles: thread t handles (row = t>>2, 16B chunk = t&3)
    int frow = t >> 2, fc = t & 3;
    uint32_t foff = (uint32_t)frow * 64 + ((fc ^ (frow & 3)) << 4);
    const float* Asrc = A + (long long)(row0 + frow) * lda + fc * 8;
    const bool bact = (BN == 128) || (t < BN * 4);
    const float* Bsrc = Bm + (long long)(col0 + frow) * ldb + fc * 8;

    uint32_t sb = smem_u32(smem);

    float acc[2][NT][4];
    #pragma unroll
    for (int i = 0; i < 2; i++)
        #pragma unroll
        for (int j = 0; j < NT; j++)
            #pragma unroll
            for (int q = 0; q < 4; q++) acc[i][j][q] = 0.0f;

    int nk = K >> 5;

    // prologue: fill stage 0
    {
        float4 a0 = *(const float4*)(Asrc);
        float4 a1 = *(const float4*)(Asrc + 4);
        uint4 hv, lv;
        cvt8h(a0, a1, hv, lv);
        *(uint4*)(smem + foff)       = hv;
        *(uint4*)(smem + ASZ + foff) = lv;
        if (bact) {
            float4 b0 = *(const float4*)(Bsrc);
            float4 b1 = *(const float4*)(Bsrc + 4);
            *(uint4*)(smem + 2 * ASZ + foff) = cvt8h_hi(b0, b1);
        }
    }
    __syncthreads();

    // ldmatrix address components (verified mapping, constant across stages)
    int arow_base = wm * 32 + (lane & 15);        // + mi*16
    int asel      = lane >> 4;                    // k half (chunk +0/+1)
    int nrow_base = wn * WN + (lane & 7) + ((lane >> 4) << 3);  // + p*16
    int bsel      = (lane >> 3) & 1;

    for (int it = 0; it < nk; it++) {
        int cur = it & 1;
        bool more = (it + 1 < nk);
        float4 la0, la1, lb0, lb1;
        if (more) {
            int k0 = (it + 1) << 5;
            la0 = *(const float4*)(Asrc + k0);
            la1 = *(const float4*)(Asrc + k0 + 4);
            if (bact) {
                lb0 = *(const float4*)(Bsrc + k0);
                lb1 = *(const float4*)(Bsrc + k0 + 4);
            }
        }

        uint32_t sA = sb + cur * STG;
        uint32_t sB = sA + 2 * ASZ;

        #pragma unroll
        for (int ks = 0; ks < 2; ks++) {
            uint32_t ah[2][4], al[2][4];
            #pragma unroll
            for (int mi = 0; mi < 2; mi++) {
                int r = arow_base + mi * 16;
                uint32_t ch = (uint32_t)(ks * 2 + asel) ^ (r & 3);
                uint32_t off = (uint32_t)r * 64 + (ch << 4);
                ldsm4(sA + off, ah[mi]);
                ldsm4(sA + ASZ + off, al[mi]);
            }
            uint32_t bh[NT][2];
            #pragma unroll
            for (int p = 0; p < NT / 2; p++) {
                int n = nrow_base + p * 16;
                uint32_t ch = (uint32_t)(ks * 2 + bsel) ^ (n & 3);
                uint32_t off = (uint32_t)n * 64 + (ch << 4);
                uint32_t rh[4];
                ldsm4(sB + off, rh);
                bh[2 * p][0] = rh[0]; bh[2 * p][1] = rh[1];
                bh[2 * p + 1][0] = rh[2]; bh[2 * p + 1][1] = rh[3];
            }
            #pragma unroll
            for (int mi = 0; mi < 2; mi++)
                #pragma unroll
                for (int ni = 0; ni < NT; ni++) {
                    mma16816(acc[mi][ni], ah[mi], bh[ni]);
                    mma16816(acc[mi][ni], al[mi], bh[ni]);
                }
        }

        if (more) {
            int nxt = cur ^ 1;
            char* st = smem + nxt * STG;
            uint4 hv, lv;
            cvt8h(la0, la1, hv, lv);
            *(uint4*)(st + foff)       = hv;
            *(uint4*)(st + ASZ + foff) = lv;
            if (bact)
                *(uint4*)(st + 2 * ASZ + foff) = cvt8h_hi(lb0, lb1);
        }
        __syncthreads();
    }

    // epilogue: c0,c1 -> (row, col..col+1); c2,c3 -> (row+8, same cols)
    #pragma unroll
    for (int mi = 0; mi < 2; mi++) {
        int r = row0 + wm * 32 + mi * 16 + (lane >> 2);
        #pragma unroll
        for (int ni = 0; ni < NT; ni++) {
            int cidx = col0 + wn * WN + ni * 8 + (lane & 3) * 2;
            float b0 = 0.f, b1 = 0.f;
            if (bias) { b0 = bias[cidx]; b1 = bias[cidx + 1]; }
            float* cp = C + (long long)r * ldc + cidx;
            *(float2*)cp = make_float2(acc[mi][ni][0] * alpha + b0,
                                       acc[mi][ni][1] * alpha + b1);
            cp += 8 * ldc;
            *(float2*)cp = make_float2(acc[mi][ni][2] * alpha + b0,
                                       acc[mi][ni][3] * alpha + b1);
        }
    }
}

// ---------------------------------------------------------------------------
// Transpose V half of kv into g_vt[(b*12+h)*64 + d][tok]  (64x64 smem tiles)
// ---------------------------------------------------------------------------
__global__ void __launch_bounds__(256)
transpose_v(const float* __restrict__ kv, float* __restrict__ vt)
{
    __shared__ float s[64][65];
    int bh = blockIdx.x;
    int b = bh / NHEADS, h = bh - b * NHEADS;
    int tk = blockIdx.y << 6;
    int t = threadIdx.x;
    int tl = t >> 2;             // 0..63
    int ds = (t & 3) << 4;       // 0,16,32,48

    const float* src = kv + ((long long)(b * SEQ + tk + tl)) * (2 * DMODEL)
                          + DMODEL + h * HDIM + ds;
    #pragma unroll
    for (int j = 0; j < 16; j += 4) {
        float4 v = *(const float4*)(src + j);
        s[tl][ds + j + 0] = v.x; s[tl][ds + j + 1] = v.y;
        s[tl][ds + j + 2] = v.z; s[tl][ds + j + 3] = v.w;
    }
    __syncthreads();

    int dl = t >> 2;
    int ts = (t & 3) << 4;
    float* dst = vt + ((long long)(bh * HDIM + dl)) * SEQ + tk + ts;
    #pragma unroll
    for (int j = 0; j < 16; j += 4) {
        float4 v;
        v.x = s[ts + j + 0][dl]; v.y = s[ts + j + 1][dl];
        v.z = s[ts + j + 2][dl]; v.w = s[ts + j + 3][dl];
        *(float4*)(dst + j) = v;
    }
}

// ---------------------------------------------------------------------------
// In-place softmax over rows of 1024. One 256-thread block per row.
// ---------------------------------------------------------------------------
__global__ void softmax_rows(float* __restrict__ attn)
{
    float* p = attn + (long long)blockIdx.x * SEQ;
    int t = threadIdx.x;
    float4 v = ((float4*)p)[t];

    __shared__ float red[8];

    float m = fmaxf(fmaxf(v.x, v.y), fmaxf(v.z, v.w));
    #pragma unroll
    for (int o = 16; o > 0; o >>= 1)
        m = fmaxf(m, __shfl_xor_sync(0xffffffffu, m, o));
    if ((t & 31) == 0) red[t >> 5] = m;
    __syncthreads();
    float bm = red[0];
    #pragma unroll
    for (int i = 1; i < 8; i++) bm = fmaxf(bm, red[i]);

    float e0 = expf(v.x - bm), e1 = expf(v.y - bm);
    float e2 = expf(v.z - bm), e3 = expf(v.w - bm);
    float s = (e0 + e1) + (e2 + e3);
    #pragma unroll
    for (int o = 16; o > 0; o >>= 1)
        s += __shfl_xor_sync(0xffffffffu, s, o);
    __syncthreads();
    if ((t & 31) == 0) red[t >> 5] = s;
    __syncthreads();
    float bs = red[0];
    #pragma unroll
    for (int i = 1; i < 8; i++) bs += red[i];

    float inv = 1.0f / bs;
    ((float4*)p)[t] = make_float4(e0 * inv, e1 * inv, e2 * inv, e3 * inv);
}

// ---------------------------------------------------------------------------
// d_in: 0=x [8,1024,768] f32, 1=q_w [768,768], 2=kv_w [1536,768],
//       3=proj_w [768,768], 4=proj_b [768], 5=H, 6=W
// d_out: out [8*1024*768] f32 followed by attn [8*12*1024*1024] f32
// ---------------------------------------------------------------------------
extern "C" void kernel_launch(void* const* d_in, const int* in_sizes, int n_in,
                              void* d_out, int out_size)
{
    const float* x   = (const float*)d_in[0];
    const float* qw  = (const float*)d_in[1];
    const float* kvw = (const float*)d_in[2];
    const float* pw  = (const float*)d_in[3];
    const float* pb  = (const float*)d_in[4];

    float* out  = (float*)d_out;
    float* attn = out + (long long)B_ * SEQ * DMODEL;

    float *gq, *gkv, *gctx, *gvt;
    cudaGetSymbolAddress((void**)&gq,   g_q);
    cudaGetSymbolAddress((void**)&gkv,  g_kv);
    cudaGetSymbolAddress((void**)&gctx, g_ctx);
    cudaGetSymbolAddress((void**)&gvt,  g_vt);

    // dynamic smem: 2 stages * (AH + AL + BH)
    const int SMEM128 = 2 * (2 * 128 * 64 + 128 * 64);  // 49152
    const int SMEM64  = 2 * (2 * 128 * 64 + 64 * 64);   // 40960
    cudaFuncSetAttribute(gemm_hmma<128>, cudaFuncAttributeMaxDynamicSharedMemorySize, SMEM128);
    cudaFuncSetAttribute(gemm_hmma<64>,  cudaFuncAttributeMaxDynamicSharedMemorySize, SMEM64);

    const int MROWS = B_ * SEQ;                 // 8192
    const long long SS = (long long)SEQ * SEQ;

    // 1) Q = x @ q_w^T           [8192, 768]
    gemm_hmma<128><<<dim3(DMODEL / 128, MROWS / 128, 1), 512, SMEM128>>>(
        x, qw, gq, nullptr,
        DMODEL, DMODEL, DMODEL, DMODEL,
        1, 0, 0, 0, 0, 0, 0, 1.0f);

    // 2) KV = x @ kv_w^T         [8192, 1536]
    gemm_hmma<128><<<dim3(2 * DMODEL / 128, MROWS / 128, 1), 512, SMEM128>>>(
        x, kvw, gkv, nullptr,
        DMODEL, DMODEL, DMODEL, 2 * DMODEL,
        1, 0, 0, 0, 0, 0, 0, 1.0f);

    // 2b) V^T per (b,h)
    transpose_v<<<dim3(B_ * NHEADS, SEQ / 64, 1), 256>>>(gkv, gvt);

    // 3) S[b,h] = 0.125 * Q_h @ K_h^T   (96 batched [1024,1024,64])
    gemm_hmma<128><<<dim3(SEQ / 128, SEQ / 128, B_ * NHEADS), 512, SMEM128>>>(
        gq, gkv, attn, nullptr,
        HDIM, DMODEL, 2 * DMODEL, SEQ,
        NHEADS,
        (long long)SEQ * DMODEL,     HDIM,        // A: per-b, per-h
        (long long)SEQ * 2 * DMODEL, HDIM,        // B (K half of kv)
        (long long)NHEADS * SS,      SS,          // C
        0.125f);

    // 4) row softmax in place
    softmax_rows<<<B_ * NHEADS * SEQ, 256>>>(attn);

    // 5) ctx[b,:,h*64..] = attn[b,h] @ Vt[b,h]^T   (NT with B = V^T [64,1024])
    gemm_hmma<64><<<dim3(1, SEQ / 128, B_ * NHEADS), 512, SMEM64>>>(
        attn, gvt, gctx, nullptr,
        SEQ, SEQ, SEQ, DMODEL,
        NHEADS,
        (long long)NHEADS * SS,          SS,                     // A
        (long long)NHEADS * HDIM * SEQ,  (long long)HDIM * SEQ,  // B
        (long long)SEQ * DMODEL,         HDIM,                   // C
        1.0f);

    // 6) out = ctx @ proj_w^T + proj_b
    gemm_hmma<128><<<dim3(DMODEL / 128, MROWS / 128, 1), 512, SMEM128>>>(
        gctx, pw, out, pb,
        DMODEL, DMODEL, DMODEL, DMODEL,
        1, 0, 0, 0, 0, 0, 0, 1.0f);
}

// round 15
// speedup vs baseline: 1.2976x; 1.1206x over previous
#include <cuda_runtime.h>
#include <cuda_fp16.h>
#include <cstdint>

#define B_      8
#define SEQ     1024
#define DMODEL  768
#define NHEADS  12
#define HDIM    64

// Scratch (allocation-free: __device__ globals)
__device__ float  g_q  [B_*SEQ*DMODEL];            // 25 MB
__device__ float  g_kv [B_*SEQ*2*DMODEL];          // 50 MB
__device__ float  g_ctx[B_*SEQ*DMODEL];            // 25 MB
__device__ float  g_vt [B_*NHEADS*HDIM*SEQ];       // 25 MB  V^T per (b,h): [64][1024]
__device__ float2 g_st [B_*NHEADS*SEQ];            // per-row (max, sumexp)

// ---------------------------------------------------------------------------
// helpers
// ---------------------------------------------------------------------------
__device__ __forceinline__ uint32_t smem_u32(const void* p) {
    uint32_t a;
    asm("{ .reg .u64 t; cvta.to.shared.u64 t, %1; cvt.u32.u64 %0, t; }"
        : "=r"(a) : "l"(p));
    return a;
}

__device__ __forceinline__ uint32_t packh2(float a, float b) {
    __half2 h = __floats2half2_rn(a, b);
    return *reinterpret_cast<uint32_t*>(&h);
}

// 8 fp32 -> 8 fp16 hi + 8 fp16 residual lo (A operand)
__device__ __forceinline__ void cvt8h(float4 f0, float4 f1, uint4& hv, uint4& lv) {
    uint32_t h0 = packh2(f0.x, f0.y);
    uint32_t h1 = packh2(f0.z, f0.w);
    uint32_t h2 = packh2(f1.x, f1.y);
    uint32_t h3 = packh2(f1.z, f1.w);
    hv = make_uint4(h0, h1, h2, h3);
    __half2 H0 = *(__half2*)&h0, H1 = *(__half2*)&h1;
    __half2 H2 = *(__half2*)&h2, H3 = *(__half2*)&h3;
    lv = make_uint4(
        packh2(f0.x - __low2float(H0), f0.y - __high2float(H0)),
        packh2(f0.z - __low2float(H1), f0.w - __high2float(H1)),
        packh2(f1.x - __low2float(H2), f1.y - __high2float(H2)),
        packh2(f1.z - __low2float(H3), f1.w - __high2float(H3)));
}

// 8 fp32 -> 8 fp16 (B operand, hi only)
__device__ __forceinline__ uint4 cvt8h_hi(float4 f0, float4 f1) {
    return make_uint4(packh2(f0.x, f0.y), packh2(f0.z, f0.w),
                      packh2(f1.x, f1.y), packh2(f1.z, f1.w));
}

__device__ __forceinline__ void ldsm4(uint32_t addr, uint32_t* r) {
    asm volatile("ldmatrix.sync.aligned.m8n8.x4.shared.b16 {%0,%1,%2,%3}, [%4];"
        : "=r"(r[0]), "=r"(r[1]), "=r"(r[2]), "=r"(r[3]) : "r"(addr));
}

__device__ __forceinline__ void mma16816(float* d, const uint32_t* a, const uint32_t* b) {
    asm volatile(
        "mma.sync.aligned.m16n8k16.row.col.f32.f16.f16.f32 "
        "{%0,%1,%2,%3},{%4,%5,%6,%7},{%8,%9},{%0,%1,%2,%3};"
        : "+f"(d[0]), "+f"(d[1]), "+f"(d[2]), "+f"(d[3])
        : "r"(a[0]), "r"(a[1]), "r"(a[2]), "r"(a[3]), "r"(b[0]), "r"(b[1]));
}

// ---------------------------------------------------------------------------
// Projection GEMM (unchanged from R14): C[128,128] = alpha*(A@B^T)(+bias).
// A split hi+lo fp16, B hi only: 2 MMAs per m16n8k16 tile. 512 threads.
// ---------------------------------------------------------------------------
template <int BN>
__global__ void __launch_bounds__(512)
gemm_hmma(const float* __restrict__ A, const float* __restrict__ Bm,
          float* __restrict__ C, const float* __restrict__ bias,
          int K, int lda, int ldb, int ldc,
          int zdiv,
          long long sAo, long long sAi,
          long long sBo, long long sBi,
          long long sCo, long long sCi,
          float alpha)
{
    extern __shared__ char smem[];
    const int ASZ = 128 * 64;
    const int BSZ = BN * 64;
    const int STG = 2 * ASZ + BSZ;
    const int WN  = BN / 4;
    const int NT  = WN / 8;

    int z  = blockIdx.z;
    int zo = z / zdiv, zi = z - zo * zdiv;
    A  += zo * sAo + zi * sAi;
    Bm += zo * sBo + zi * sBi;
    C  += zo * sCo + zi * sCi;

    int t    = threadIdx.x;
    int warp = t >> 5, lane = t & 31;
    int wm   = warp >> 2, wn = warp & 3;

    int row0 = blockIdx.y << 7;
    int col0 = blockIdx.x * BN;

    int frow = t >> 2, fc = t & 3;
    uint32_t foff = (uint32_t)frow * 64 + ((fc ^ (frow & 3)) << 4);
    const float* Asrc = A + (long long)(row0 + frow) * lda + fc * 8;
    const bool bact = (BN == 128) || (t < BN * 4);
    const float* Bsrc = Bm + (long long)(col0 + frow) * ldb + fc * 8;

    uint32_t sb = smem_u32(smem);

    float acc[2][NT][4];
    #pragma unroll
    for (int i = 0; i < 2; i++)
        #pragma unroll
        for (int j = 0; j < NT; j++)
            #pragma unroll
            for (int q = 0; q < 4; q++) acc[i][j][q] = 0.0f;

    int nk = K >> 5;

    {
        float4 a0 = *(const float4*)(Asrc);
        float4 a1 = *(const float4*)(Asrc + 4);
        uint4 hv, lv;
        cvt8h(a0, a1, hv, lv);
        *(uint4*)(smem + foff)       = hv;
        *(uint4*)(smem + ASZ + foff) = lv;
        if (bact) {
            float4 b0 = *(const float4*)(Bsrc);
            float4 b1 = *(const float4*)(Bsrc + 4);
            *(uint4*)(smem + 2 * ASZ + foff) = cvt8h_hi(b0, b1);
        }
    }
    __syncthreads();

    int arow_base = wm * 32 + (lane & 15);
    int asel      = lane >> 4;
    int nrow_base = wn * WN + (lane & 7) + ((lane >> 4) << 3);
    int bsel      = (lane >> 3) & 1;

    for (int it = 0; it < nk; it++) {
        int cur = it & 1;
        bool more = (it + 1 < nk);
        float4 la0, la1, lb0, lb1;
        if (more) {
            int k0 = (it + 1) << 5;
            la0 = *(const float4*)(Asrc + k0);
            la1 = *(const float4*)(Asrc + k0 + 4);
            if (bact) {
                lb0 = *(const float4*)(Bsrc + k0);
                lb1 = *(const float4*)(Bsrc + k0 + 4);
            }
        }

        uint32_t sA = sb + cur * STG;
        uint32_t sB = sA + 2 * ASZ;

        #pragma unroll
        for (int ks = 0; ks < 2; ks++) {
            uint32_t ah[2][4], al[2][4];
            #pragma unroll
            for (int mi = 0; mi < 2; mi++) {
                int r = arow_base + mi * 16;
                uint32_t ch = (uint32_t)(ks * 2 + asel) ^ (r & 3);
                uint32_t off = (uint32_t)r * 64 + (ch << 4);
                ldsm4(sA + off, ah[mi]);
                ldsm4(sA + ASZ + off, al[mi]);
            }
            uint32_t bh[NT][2];
            #pragma unroll
            for (int p = 0; p < NT / 2; p++) {
                int n = nrow_base + p * 16;
                uint32_t ch = (uint32_t)(ks * 2 + bsel) ^ (n & 3);
                uint32_t off = (uint32_t)n * 64 + (ch << 4);
                uint32_t rh[4];
                ldsm4(sB + off, rh);
                bh[2 * p][0] = rh[0]; bh[2 * p][1] = rh[1];
                bh[2 * p + 1][0] = rh[2]; bh[2 * p + 1][1] = rh[3];
            }
            #pragma unroll
            for (int mi = 0; mi < 2; mi++)
                #pragma unroll
                for (int ni = 0; ni < NT; ni++) {
                    mma16816(acc[mi][ni], ah[mi], bh[ni]);
                    mma16816(acc[mi][ni], al[mi], bh[ni]);
                }
        }

        if (more) {
            int nxt = cur ^ 1;
            char* st = smem + nxt * STG;
            uint4 hv, lv;
            cvt8h(la0, la1, hv, lv);
            *(uint4*)(st + foff)       = hv;
            *(uint4*)(st + ASZ + foff) = lv;
            if (bact)
                *(uint4*)(st + 2 * ASZ + foff) = cvt8h_hi(lb0, lb1);
        }
        __syncthreads();
    }

    #pragma unroll
    for (int mi = 0; mi < 2; mi++) {
        int r = row0 + wm * 32 + mi * 16 + (lane >> 2);
        #pragma unroll
        for (int ni = 0; ni < NT; ni++) {
            int cidx = col0 + wn * WN + ni * 8 + (lane & 3) * 2;
            float b0 = 0.f, b1 = 0.f;
            if (bias) { b0 = bias[cidx]; b1 = bias[cidx + 1]; }
            float* cp = C + (long long)r * ldc + cidx;
            *(float2*)cp = make_float2(acc[mi][ni][0] * alpha + b0,
                                       acc[mi][ni][1] * alpha + b1);
            cp += 8 * ldc;
            *(float2*)cp = make_float2(acc[mi][ni][2] * alpha + b0,
                                       acc[mi][ni][3] * alpha + b1);
        }
    }
}

// ---------------------------------------------------------------------------
// S kernel: per CTA, Q row-block (128x64) resident in smem; loop over the 8
// column tiles of S[b,h] = 0.125 * Q @ K^T, double-buffering K tiles.
// Writes S and exact per-row softmax stats (online max/sumexp across all
// 1024 cols, which this CTA sees in full).
// ---------------------------------------------------------------------------
__global__ void __launch_bounds__(512)
s_gemm(const float* __restrict__ Q, const float* __restrict__ Kv,
       float* __restrict__ Sout, float2* __restrict__ stats)
{
    extern __shared__ char smem[];
    const int ATS  = 8192;        // one 128x(32-k) fp16 tile
    const int BOFF = 4 * ATS;     // A: AH0|AL0|AH1|AL1 (32 KB)
    const int SOFF = BOFF + 4 * ATS;  // B: 2 bufs x 2 ktiles (32 KB); stats 4 KB

    int z = blockIdx.z;                 // bh
    int b = z / NHEADS, h = z - b * NHEADS;
    int row0 = blockIdx.y << 7;

    int t = threadIdx.x, warp = t >> 5, lane = t & 31;
    int wm = warp >> 2, wn = warp & 3;

    int frow = t >> 2, fc = t & 3;
    uint32_t foff = (uint32_t)frow * 64 + ((fc ^ (frow & 3)) << 4);

    const float* Asrc = Q + (long long)(b * SEQ + row0 + frow) * DMODEL + h * HDIM + fc * 8;
    const float* Bcol = Kv + (long long)(b * SEQ) * (2 * DMODEL) + h * HDIM + fc * 8;
    float* Sb = Sout + (long long)z * SEQ * SEQ;

    uint32_t sb = smem_u32(smem);

    // prologue: A resident (2 ktiles, hi+lo) + B tile 0
    {
        float4 a0 = *(const float4*)(Asrc);
        float4 a1 = *(const float4*)(Asrc + 4);
        uint4 hv, lv;
        cvt8h(a0, a1, hv, lv);
        *(uint4*)(smem + 0 * ATS + foff) = hv;
        *(uint4*)(smem + 1 * ATS + foff) = lv;
        float4 a2 = *(const float4*)(Asrc + 32);
        float4 a3 = *(const float4*)(Asrc + 36);
        cvt8h(a2, a3, hv, lv);
        *(uint4*)(smem + 2 * ATS + foff) = hv;
        *(uint4*)(smem + 3 * ATS + foff) = lv;
        const float* Bs = Bcol + (long long)frow * (2 * DMODEL);
        float4 b0 = *(const float4*)(Bs);
        float4 b1 = *(const float4*)(Bs + 4);
        *(uint4*)(smem + BOFF + foff) = cvt8h_hi(b0, b1);
        float4 b2 = *(const float4*)(Bs + 32);
        float4 b3 = *(const float4*)(Bs + 36);
        *(uint4*)(smem + BOFF + ATS + foff) = cvt8h_hi(b2, b3);
    }
    __syncthreads();

    int arow_base = wm * 32 + (lane & 15);
    int asel      = lane >> 4;
    int nrow_base = wn * 32 + (lane & 7) + ((lane >> 4) << 3);
    int bsel      = (lane >> 3) & 1;

    // online stats per thread: slot [mi][half] (half: +0 / +8 row)
    float mrun[2][2], srun[2][2];
    #pragma unroll
    for (int i = 0; i < 2; i++)
        #pragma unroll
        for (int j = 0; j < 2; j++) { mrun[i][j] = -1e30f; srun[i][j] = 0.f; }

    for (int nt = 0; nt < 8; nt++) {
        int cur = nt & 1;
        bool more = (nt < 7);
        float4 nb0, nb1, nb2, nb3;
        if (more) {
            const float* Bs = Bcol + (long long)((nt + 1) * 128 + frow) * (2 * DMODEL);
            nb0 = *(const float4*)(Bs);
            nb1 = *(const float4*)(Bs + 4);
            nb2 = *(const float4*)(Bs + 32);
            nb3 = *(const float4*)(Bs + 36);
        }

        float acc[2][4][4];
        #pragma unroll
        for (int i = 0; i < 2; i++)
            #pragma unroll
            for (int j = 0; j < 4; j++)
                #pragma unroll
                for (int q = 0; q < 4; q++) acc[i][j][q] = 0.f;

        uint32_t sBb = sb + BOFF + cur * 2 * ATS;
        #pragma unroll
        for (int kt = 0; kt < 2; kt++) {
            uint32_t sA  = sb + kt * 2 * ATS;
            uint32_t sBk = sBb + kt * ATS;
            #pragma unroll
            for (int ks = 0; ks < 2; ks++) {
                uint32_t ah[2][4], al[2][4];
                #pragma unroll
                for (int mi = 0; mi < 2; mi++) {
                    int r = arow_base + mi * 16;
                    uint32_t ch = (uint32_t)(ks * 2 + asel) ^ (r & 3);
                    uint32_t off = (uint32_t)r * 64 + (ch << 4);
                    ldsm4(sA + off, ah[mi]);
                    ldsm4(sA + ATS + off, al[mi]);
                }
                uint32_t bh[4][2];
                #pragma unroll
                for (int p = 0; p < 2; p++) {
                    int n = nrow_base + p * 16;
                    uint32_t ch = (uint32_t)(ks * 2 + bsel) ^ (n & 3);
                    uint32_t off = (uint32_t)n * 64 + (ch << 4);
                    uint32_t rh[4];
                    ldsm4(sBk + off, rh);
                    bh[2 * p][0] = rh[0]; bh[2 * p][1] = rh[1];
                    bh[2 * p + 1][0] = rh[2]; bh[2 * p + 1][1] = rh[3];
                }
                #pragma unroll
                for (int mi = 0; mi < 2; mi++)
                    #pragma unroll
                    for (int ni = 0; ni < 4; ni++) {
                        mma16816(acc[mi][ni], ah[mi], bh[ni]);
                        mma16816(acc[mi][ni], al[mi], bh[ni]);
                    }
            }
        }

        // epilogue: scale, STG, online stats
        int colb = nt * 128;
        #pragma unroll
        for (int mi = 0; mi < 2; mi++) {
            #pragma unroll
            for (int ni = 0; ni < 4; ni++)
                #pragma unroll
                for (int q = 0; q < 4; q++) acc[mi][ni][q] *= 0.125f;

            int r = row0 + wm * 32 + mi * 16 + (lane >> 2);
            #pragma unroll
            for (int hq = 0; hq < 2; hq++) {
                float tm = -1e30f;
                #pragma unroll
                for (int ni = 0; ni < 4; ni++)
                    tm = fmaxf(tm, fmaxf(acc[mi][ni][2 * hq], acc[mi][ni][2 * hq + 1]));
                float nm = fmaxf(mrun[mi][hq], tm);
                float s = srun[mi][hq] * __expf(mrun[mi][hq] - nm);
                #pragma unroll
                for (int ni = 0; ni < 4; ni++)
                    s += __expf(acc[mi][ni][2 * hq] - nm) + __expf(acc[mi][ni][2 * hq + 1] - nm);
                mrun[mi][hq] = nm;
                srun[mi][hq] = s;
            }
            #pragma unroll
            for (int ni = 0; ni < 4; ni++) {
                int c = colb + wn * 32 + ni * 8 + (lane & 3) * 2;
                float* cp = Sb + (long long)r * SEQ + c;
                *(float2*)cp = make_float2(acc[mi][ni][0], acc[mi][ni][1]);
                *(float2*)(cp + 8 * SEQ) = make_float2(acc[mi][ni][2], acc[mi][ni][3]);
            }
        }

        if (more) {
            char* st = smem + BOFF + (cur ^ 1) * 2 * ATS;
            *(uint4*)(st + foff)       = cvt8h_hi(nb0, nb1);
            *(uint4*)(st + ATS + foff) = cvt8h_hi(nb2, nb3);
            __syncthreads();
        }
    }

    // final stats reduce: lanes (lane&3) then wn warps via smem
    #pragma unroll
    for (int mi = 0; mi < 2; mi++)
        #pragma unroll
        for (int hq = 0; hq < 2; hq++) {
            float m = mrun[mi][hq], s = srun[mi][hq];
            #pragma unroll
            for (int o = 1; o <= 2; o <<= 1) {
                float mo = __shfl_xor_sync(0xffffffffu, m, o);
                float so = __shfl_xor_sync(0xffffffffu, s, o);
                float nm = fmaxf(m, mo);
                s = s * __expf(m - nm) + so * __expf(mo - nm);
                m = nm;
            }
            if ((lane & 3) == 0) {
                int rl = wm * 32 + mi * 16 + hq * 8 + (lane >> 2);
                *(float2*)(smem + SOFF + (rl * 4 + wn) * 8) = make_float2(m, s);
            }
        }
    __syncthreads();
    if (t < 128) {
        float2 p0 = *(float2*)(smem + SOFF + (t * 4 + 0) * 8);
        float2 p1 = *(float2*)(smem + SOFF + (t * 4 + 1) * 8);
        float2 p2 = *(float2*)(smem + SOFF + (t * 4 + 2) * 8);
        float2 p3 = *(float2*)(smem + SOFF + (t * 4 + 3) * 8);
        float m = fmaxf(fmaxf(p0.x, p1.x), fmaxf(p2.x, p3.x));
        float s = p0.y * __expf(p0.x - m) + p1.y * __expf(p1.x - m)
                + p2.y * __expf(p2.x - m) + p3.y * __expf(p3.x - m);
        stats[(long long)z * SEQ + row0 + t] = make_float2(m, s);
    }
}

// ---------------------------------------------------------------------------
// Fused normalize + AV: reads raw S, computes p = exp(s-m)/sum, writes attn
// in place, and accumulates ctx = p @ V^T (B = Vt, hi-only fp16; A=p hi+lo).
// Shape: BM=128, BN=64, BK=32, 512 threads (gemm_hmma<64> skeleton).
// ---------------------------------------------------------------------------
__global__ void __launch_bounds__(512)
pav_gemm(float* __restrict__ Sm, const float* __restrict__ Vt,
         const float2* __restrict__ stats, float* __restrict__ Ctx)
{
    extern __shared__ char smem[];
    const int ASZ = 128 * 64;
    const int BSZ = 64 * 64;
    const int STG = 2 * ASZ + BSZ;

    int z = blockIdx.z;                 // bh
    int b = z / NHEADS, h = z - b * NHEADS;
    int row0 = blockIdx.y << 7;

    int t = threadIdx.x, warp = t >> 5, lane = t & 31;
    int wm = warp >> 2, wn = warp & 3;

    int frow = t >> 2, fc = t & 3;
    uint32_t foff = (uint32_t)frow * 64 + ((fc ^ (frow & 3)) << 4);

    float* Asrc = Sm + (long long)z * SEQ * SEQ + (long long)(row0 + frow) * SEQ + fc * 8;
    const bool bact = (t < 256);
    const float* Bsrc = Vt + (long long)z * HDIM * SEQ + (long long)frow * SEQ + fc * 8;

    float2 st = stats[(long long)z * SEQ + row0 + frow];
    float mrow = st.x, inv = 1.0f / st.y;

    uint32_t sb = smem_u32(smem);

    float acc[2][2][4];
    #pragma unroll
    for (int i = 0; i < 2; i++)
        #pragma unroll
        for (int j = 0; j < 2; j++)
            #pragma unroll
            for (int q = 0; q < 4; q++) acc[i][j][q] = 0.0f;

    // prologue: tile 0 (exp + write + STS)
    {
        float4 a0 = *(const float4*)(Asrc);
        float4 a1 = *(const float4*)(Asrc + 4);
        a0.x = __expf(a0.x - mrow) * inv; a0.y = __expf(a0.y - mrow) * inv;
        a0.z = __expf(a0.z - mrow) * inv; a0.w = __expf(a0.w - mrow) * inv;
        a1.x = __expf(a1.x - mrow) * inv; a1.y = __expf(a1.y - mrow) * inv;
        a1.z = __expf(a1.z - mrow) * inv; a1.w = __expf(a1.w - mrow) * inv;
        *(float4*)(Asrc)     = a0;
        *(float4*)(Asrc + 4) = a1;
        uint4 hv, lv;
        cvt8h(a0, a1, hv, lv);
        *(uint4*)(smem + foff)       = hv;
        *(uint4*)(smem + ASZ + foff) = lv;
        if (bact) {
            float4 b0 = *(const float4*)(Bsrc);
            float4 b1 = *(const float4*)(Bsrc + 4);
            *(uint4*)(smem + 2 * ASZ + foff) = cvt8h_hi(b0, b1);
        }
    }
    __syncthreads();

    int arow_base = wm * 32 + (lane & 15);
    int asel      = lane >> 4;
    int nrow_base = wn * 16 + (lane & 7) + ((lane >> 4) << 3);
    int bsel      = (lane >> 3) & 1;

    const int nk = SEQ / 32;   // 32
    for (int it = 0; it < nk; it++) {
        int cur = it & 1;
        bool more = (it + 1 < nk);
        float4 la0, la1, lb0, lb1;
        if (more) {
            int k0 = (it + 1) << 5;
            la0 = *(const float4*)(Asrc + k0);
            la1 = *(const float4*)(Asrc + k0 + 4);
            if (bact) {
                lb0 = *(const float4*)(Bsrc + k0);
                lb1 = *(const float4*)(Bsrc + k0 + 4);
            }
        }

        uint32_t sA = sb + cur * STG;
        uint32_t sB = sA + 2 * ASZ;

        #pragma unroll
        for (int ks = 0; ks < 2; ks++) {
            uint32_t ah[2][4], al[2][4];
            #pragma unroll
            for (int mi = 0; mi < 2; mi++) {
                int r = arow_base + mi * 16;
                uint32_t ch = (uint32_t)(ks * 2 + asel) ^ (r & 3);
                uint32_t off = (uint32_t)r * 64 + (ch << 4);
                ldsm4(sA + off, ah[mi]);
                ldsm4(sA + ASZ + off, al[mi]);
            }
            uint32_t bh[2][2];
            {
                int n = nrow_base;
                uint32_t ch = (uint32_t)(ks * 2 + bsel) ^ (n & 3);
                uint32_t off = (uint32_t)n * 64 + (ch << 4);
                uint32_t rh[4];
                ldsm4(sB + off, rh);
                bh[0][0] = rh[0]; bh[0][1] = rh[1];
                bh[1][0] = rh[2]; bh[1][1] = rh[3];
            }
            #pragma unroll
            for (int mi = 0; mi < 2; mi++)
                #pragma unroll
                for (int ni = 0; ni < 2; ni++) {
                    mma16816(acc[mi][ni], ah[mi], bh[ni]);
                    mma16816(acc[mi][ni], al[mi], bh[ni]);
                }
        }

        if (more) {
            int k0 = (it + 1) << 5;
            la0.x = __expf(la0.x - mrow) * inv; la0.y = __expf(la0.y - mrow) * inv;
            la0.z = __expf(la0.z - mrow) * inv; la0.w = __expf(la0.w - mrow) * inv;
            la1.x = __expf(la1.x - mrow) * inv; la1.y = __expf(la1.y - mrow) * inv;
            la1.z = __expf(la1.z - mrow) * inv; la1.w = __expf(la1.w - mrow) * inv;
            *(float4*)(Asrc + k0)     = la0;
            *(float4*)(Asrc + k0 + 4) = la1;
            char* stg = smem + (cur ^ 1) * STG;
            uint4 hv, lv;
            cvt8h(la0, la1, hv, lv);
            *(uint4*)(stg + foff)       = hv;
            *(uint4*)(stg + ASZ + foff) = lv;
            if (bact)
                *(uint4*)(stg + 2 * ASZ + foff) = cvt8h_hi(lb0, lb1);
        }
        __syncthreads();
    }

    // epilogue -> ctx[b, row, h*64 + c]
    float* Cb = Ctx + (long long)(b * SEQ) * DMODEL + h * HDIM;
    #pragma unroll
    for (int mi = 0; mi < 2; mi++) {
        int r = row0 + wm * 32 + mi * 16 + (lane >> 2);
        #pragma unroll
        for (int ni = 0; ni < 2; ni++) {
            int cidx = wn * 16 + ni * 8 + (lane & 3) * 2;
            float* cp = Cb + (long long)r * DMODEL + cidx;
            *(float2*)cp = make_float2(acc[mi][ni][0], acc[mi][ni][1]);
            cp += 8 * DMODEL;
            *(float2*)cp = make_float2(acc[mi][ni][2], acc[mi][ni][3]);
        }
    }
}

// ---------------------------------------------------------------------------
// Transpose V half of kv into g_vt[(b*12+h)*64 + d][tok]
// ---------------------------------------------------------------------------
__global__ void __launch_bounds__(256)
transpose_v(const float* __restrict__ kv, float* __restrict__ vt)
{
    __shared__ float s[64][65];
    int bh = blockIdx.x;
    int b = bh / NHEADS, h = bh - b * NHEADS;
    int tk = blockIdx.y << 6;
    int t = threadIdx.x;
    int tl = t >> 2;
    int ds = (t & 3) << 4;

    const float* src = kv + ((long long)(b * SEQ + tk + tl)) * (2 * DMODEL)
                          + DMODEL + h * HDIM + ds;
    #pragma unroll
    for (int j = 0; j < 16; j += 4) {
        float4 v = *(const float4*)(src + j);
        s[tl][ds + j + 0] = v.x; s[tl][ds + j + 1] = v.y;
        s[tl][ds + j + 2] = v.z; s[tl][ds + j + 3] = v.w;
    }
    __syncthreads();

    int dl = t >> 2;
    int ts = (t & 3) << 4;
    float* dst = vt + ((long long)(bh * HDIM + dl)) * SEQ + tk + ts;
    #pragma unroll
    for (int j = 0; j < 16; j += 4) {
        float4 v;
        v.x = s[ts + j + 0][dl]; v.y = s[ts + j + 1][dl];
        v.z = s[ts + j + 2][dl]; v.w = s[ts + j + 3][dl];
        *(float4*)(dst + j) = v;
    }
}

// ---------------------------------------------------------------------------
// d_in: 0=x [8,1024,768] f32, 1=q_w, 2=kv_w, 3=proj_w, 4=proj_b, 5=H, 6=W
// d_out: out [8*1024*768] f32 followed by attn [8*12*1024*1024] f32
// ---------------------------------------------------------------------------
extern "C" void kernel_launch(void* const* d_in, const int* in_sizes, int n_in,
                              void* d_out, int out_size)
{
    const float* x   = (const float*)d_in[0];
    const float* qw  = (const float*)d_in[1];
    const float* kvw = (const float*)d_in[2];
    const float* pw  = (const float*)d_in[3];
    const float* pb  = (const float*)d_in[4];

    float* out  = (float*)d_out;
    float* attn = out + (long long)B_ * SEQ * DMODEL;

    float *gq, *gkv, *gctx, *gvt;
    float2* gst;
    cudaGetSymbolAddress((void**)&gq,   g_q);
    cudaGetSymbolAddress((void**)&gkv,  g_kv);
    cudaGetSymbolAddress((void**)&gctx, g_ctx);
    cudaGetSymbolAddress((void**)&gvt,  g_vt);
    cudaGetSymbolAddress((void**)&gst,  g_st);

    const int SMEM128 = 2 * (2 * 128 * 64 + 128 * 64);      // 49152
    const int SMEM_S  = 8 * 8192 + 4096;                    // 69632
    const int SMEM_PAV = 2 * (2 * 128 * 64 + 64 * 64);      // 40960
    cudaFuncSetAttribute(gemm_hmma<128>, cudaFuncAttributeMaxDynamicSharedMemorySize, SMEM128);
    cudaFuncSetAttribute(s_gemm,   cudaFuncAttributeMaxDynamicSharedMemorySize, SMEM_S);
    cudaFuncSetAttribute(pav_gemm, cudaFuncAttributeMaxDynamicSharedMemorySize, SMEM_PAV);

    const int MROWS = B_ * SEQ;                 // 8192

    // 1) Q = x @ q_w^T
    gemm_hmma<128><<<dim3(DMODEL / 128, MROWS / 128, 1), 512, SMEM128>>>(
        x, qw, gq, nullptr,
        DMODEL, DMODEL, DMODEL, DMODEL,
        1, 0, 0, 0, 0, 0, 0, 1.0f);

    // 2) KV = x @ kv_w^T
    gemm_hmma<128><<<dim3(2 * DMODEL / 128, MROWS / 128, 1), 512, SMEM128>>>(
        x, kvw, gkv, nullptr,
        DMODEL, DMODEL, DMODEL, 2 * DMODEL,
        1, 0, 0, 0, 0, 0, 0, 1.0f);

    // 2b) V^T per (b,h)
    transpose_v<<<dim3(B_ * NHEADS, SEQ / 64, 1), 256>>>(gkv, gvt);

    // 3) S = 0.125 * Q @ K^T  (+ per-row softmax stats)
    s_gemm<<<dim3(1, SEQ / 128, B_ * NHEADS), 512, SMEM_S>>>(gq, gkv, attn, gst);

    // 4) fused: attn = softmax(S) written in place, ctx = attn @ V
    pav_gemm<<<dim3(1, SEQ / 128, B_ * NHEADS), 512, SMEM_PAV>>>(attn, gvt, gst, gctx);

    // 5) out = ctx @ proj_w^T + proj_b
    gemm_hmma<128><<<dim3(DMODEL / 128, MROWS / 128, 1), 512, SMEM128>>>(
        gctx, pw, out, pb,
        DMODEL, DMODEL, DMODEL, DMODEL,
        1, 0, 0, 0, 0, 0, 0, 1.0f);
}

// round 16
// speedup vs baseline: 1.5924x; 1.2272x over previous
#include <cuda_runtime.h>
#include <cuda_fp16.h>
#include <cstdint>

#define B_      8
#define SEQ     1024
#define DMODEL  768
#define NHEADS  12
#define HDIM    64
#define BH_     (B_*NHEADS)

// fp16 scratch (allocation-free: __device__ globals)
__device__ __half g_xh  [B_*SEQ*DMODEL];
__device__ __half g_xl  [B_*SEQ*DMODEL];
__device__ __half g_qwh [DMODEL*DMODEL];
__device__ __half g_kvwh[2*DMODEL*DMODEL];
__device__ __half g_pwh [DMODEL*DMODEL];
__device__ __half g_qh  [B_*SEQ*DMODEL];
__device__ __half g_ql  [B_*SEQ*DMODEL];
__device__ __half g_kvh [B_*SEQ*2*DMODEL];
__device__ __half g_vth [BH_*HDIM*SEQ];
__device__ __half g_ctxh[B_*SEQ*DMODEL];
__device__ __half g_ctxl[B_*SEQ*DMODEL];
__device__ float2 g_st  [BH_*SEQ];

// ---------------------------------------------------------------------------
// helpers
// ---------------------------------------------------------------------------
__device__ __forceinline__ uint32_t smem_u32(const void* p) {
    uint32_t a;
    asm("{ .reg .u64 t; cvta.to.shared.u64 t, %1; cvt.u32.u64 %0, t; }"
        : "=r"(a) : "l"(p));
    return a;
}

__device__ __forceinline__ uint32_t packh2(float a, float b) {
    __half2 h = __floats2half2_rn(a, b);
    return *reinterpret_cast<uint32_t*>(&h);
}

__device__ __forceinline__ void cvt8h(float4 f0, float4 f1, uint4& hv, uint4& lv) {
    uint32_t h0 = packh2(f0.x, f0.y);
    uint32_t h1 = packh2(f0.z, f0.w);
    uint32_t h2 = packh2(f1.x, f1.y);
    uint32_t h3 = packh2(f1.z, f1.w);
    hv = make_uint4(h0, h1, h2, h3);
    __half2 H0 = *(__half2*)&h0, H1 = *(__half2*)&h1;
    __half2 H2 = *(__half2*)&h2, H3 = *(__half2*)&h3;
    lv = make_uint4(
        packh2(f0.x - __low2float(H0), f0.y - __high2float(H0)),
        packh2(f0.z - __low2float(H1), f0.w - __high2float(H1)),
        packh2(f1.x - __low2float(H2), f1.y - __high2float(H2)),
        packh2(f1.z - __low2float(H3), f1.w - __high2float(H3)));
}

__device__ __forceinline__ void ldsm4(uint32_t addr, uint32_t* r) {
    asm volatile("ldmatrix.sync.aligned.m8n8.x4.shared.b16 {%0,%1,%2,%3}, [%4];"
        : "=r"(r[0]), "=r"(r[1]), "=r"(r[2]), "=r"(r[3]) : "r"(addr));
}

__device__ __forceinline__ void mma16816(float* d, const uint32_t* a, const uint32_t* b) {
    asm volatile(
        "mma.sync.aligned.m16n8k16.row.col.f32.f16.f16.f32 "
        "{%0,%1,%2,%3},{%4,%5,%6,%7},{%8,%9},{%0,%1,%2,%3};"
        : "+f"(d[0]), "+f"(d[1]), "+f"(d[2]), "+f"(d[3])
        : "r"(a[0]), "r"(a[1]), "r"(a[2]), "r"(a[3]), "r"(b[0]), "r"(b[1]));
}

__device__ __forceinline__ void cpa16(uint32_t dst, const void* src) {
    asm volatile("cp.async.cg.shared.global [%0], [%1], 16;"
                 :: "r"(dst), "l"(src) : "memory");
}
#define CPA_COMMIT() asm volatile("cp.async.commit_group;" ::: "memory")
template<int N> __device__ __forceinline__ void cpa_wait() {
    asm volatile("cp.async.wait_group %0;" :: "n"(N) : "memory");
}

// ---------------------------------------------------------------------------
// fp32 -> fp16 hi (+ optional lo) split, 8 floats per thread
// ---------------------------------------------------------------------------
__global__ void cvt_split(const float* __restrict__ src, __half* __restrict__ h,
                          __half* __restrict__ l, int n8)
{
    int i = blockIdx.x * blockDim.x + threadIdx.x;
    if (i >= n8) return;
    const float4* s = (const float4*)src + 2 * i;
    float4 f0 = s[0], f1 = s[1];
    uint4 hv, lv;
    cvt8h(f0, f1, hv, lv);
    ((uint4*)h)[i] = hv;
    if (l) ((uint4*)l)[i] = lv;
}

// ---------------------------------------------------------------------------
// Projection GEMM: C[128,128] = A @ B^T (+bias). All operands pre-converted
// fp16 (A hi+lo, B hi). cp.async 4-stage pipeline. Outputs fp32 C and/or
// fp16 hi(+lo) pair. 512 threads.
// ---------------------------------------------------------------------------
__global__ void __launch_bounds__(512)
proj_f16(const __half* __restrict__ Ah, const __half* __restrict__ Al,
         const __half* __restrict__ Bh,
         float* __restrict__ Cf, const float* __restrict__ bias,
         __half* __restrict__ Ch, __half* __restrict__ Cl,
         int K, int ldA, int ldB, int ldc)
{
    extern __shared__ char smem[];
    const int TSZ = 8192;          // one 128x32 fp16 tile
    const int STG = 3 * TSZ;       // AH | AL | BH per stage

    int t = threadIdx.x, warp = t >> 5, lane = t & 31;
    int wm = warp >> 2, wn = warp & 3;
    int row0 = blockIdx.y << 7, col0 = blockIdx.x << 7;
    int frow = t >> 2, fc = t & 3;
    uint32_t foff = (uint32_t)frow * 64 + ((fc ^ (frow & 3)) << 4);

    const __half* As_h = Ah + (long long)(row0 + frow) * ldA + fc * 8;
    const __half* As_l = Al + (long long)(row0 + frow) * ldA + fc * 8;
    const __half* Bs   = Bh + (long long)(col0 + frow) * ldB + fc * 8;
    uint32_t sb = smem_u32(smem);
    int nk = K >> 5;

    float acc[2][4][4];
    #pragma unroll
    for (int i = 0; i < 2; i++)
        #pragma unroll
        for (int j = 0; j < 4; j++)
            #pragma unroll
            for (int q = 0; q < 4; q++) acc[i][j][q] = 0.0f;

    // prologue: stages 0..2
    #pragma unroll
    for (int st = 0; st < 3; st++) {
        uint32_t d = sb + st * STG + foff;
        cpa16(d,           As_h + st * 32);
        cpa16(d + TSZ,     As_l + st * 32);
        cpa16(d + 2 * TSZ, Bs   + st * 32);
        CPA_COMMIT();
    }

    int arow_base = wm * 32 + (lane & 15);
    int asel      = lane >> 4;
    int nrow_base = wn * 32 + (lane & 7) + ((lane >> 4) << 3);
    int bsel      = (lane >> 3) & 1;

    for (int it = 0; it < nk; it++) {
        cpa_wait<2>();
        __syncthreads();
        int ft = it + 3;
        if (ft < nk) {
            uint32_t d = sb + (ft & 3) * STG + foff;
            cpa16(d,           As_h + ft * 32);
            cpa16(d + TSZ,     As_l + ft * 32);
            cpa16(d + 2 * TSZ, Bs   + ft * 32);
        }
        CPA_COMMIT();

        uint32_t sA = sb + (it & 3) * STG;
        uint32_t sB = sA + 2 * TSZ;

        #pragma unroll
        for (int ks = 0; ks < 2; ks++) {
            uint32_t ah[2][4], al[2][4];
            #pragma unroll
            for (int mi = 0; mi < 2; mi++) {
                int r = arow_base + mi * 16;
                uint32_t ch = (uint32_t)(ks * 2 + asel) ^ (r & 3);
                uint32_t off = (uint32_t)r * 64 + (ch << 4);
                ldsm4(sA + off, ah[mi]);
                ldsm4(sA + TSZ + off, al[mi]);
            }
            uint32_t bq[4][2];
            #pragma unroll
            for (int p = 0; p < 2; p++) {
                int n = nrow_base + p * 16;
                uint32_t ch = (uint32_t)(ks * 2 + bsel) ^ (n & 3);
                uint32_t off = (uint32_t)n * 64 + (ch << 4);
                uint32_t rh[4];
                ldsm4(sB + off, rh);
                bq[2 * p][0] = rh[0]; bq[2 * p][1] = rh[1];
                bq[2 * p + 1][0] = rh[2]; bq[2 * p + 1][1] = rh[3];
            }
            #pragma unroll
            for (int mi = 0; mi < 2; mi++)
                #pragma unroll
                for (int ni = 0; ni < 4; ni++) {
                    mma16816(acc[mi][ni], ah[mi], bq[ni]);
                    mma16816(acc[mi][ni], al[mi], bq[ni]);
                }
        }
    }

    #pragma unroll
    for (int mi = 0; mi < 2; mi++) {
        int r = row0 + wm * 32 + mi * 16 + (lane >> 2);
        #pragma unroll
        for (int ni = 0; ni < 4; ni++) {
            int cidx = col0 + wn * 32 + ni * 8 + (lane & 3) * 2;
            float v0 = acc[mi][ni][0], v1 = acc[mi][ni][1];
            float v2 = acc[mi][ni][2], v3 = acc[mi][ni][3];
            if (Cf) {
                float b0 = bias ? bias[cidx] : 0.f;
                float b1 = bias ? bias[cidx + 1] : 0.f;
                *(float2*)(Cf + (long long)r * ldc + cidx) = make_float2(v0 + b0, v1 + b1);
                *(float2*)(Cf + (long long)(r + 8) * ldc + cidx) = make_float2(v2 + b0, v3 + b1);
            }
            if (Ch) {
                uint32_t h0 = packh2(v0, v1), h1 = packh2(v2, v3);
                *(uint32_t*)(Ch + (long long)r * ldc + cidx) = h0;
                *(uint32_t*)(Ch + (long long)(r + 8) * ldc + cidx) = h1;
                if (Cl) {
                    __half2 H0 = *(__half2*)&h0, H1 = *(__half2*)&h1;
                    *(uint32_t*)(Cl + (long long)r * ldc + cidx) =
                        packh2(v0 - __low2float(H0), v1 - __high2float(H0));
                    *(uint32_t*)(Cl + (long long)(r + 8) * ldc + cidx) =
                        packh2(v2 - __low2float(H1), v3 - __high2float(H1));
                }
            }
        }
    }
}

// ---------------------------------------------------------------------------
// S kernel: A = Q (hi+lo fp16) resident; B = K tiles (fp16) via cp.async
// triple buffer. Writes S fp32 + exact per-row softmax stats.
// ---------------------------------------------------------------------------
__global__ void __launch_bounds__(512)
s_gemm(const __half* __restrict__ Qh, const __half* __restrict__ Ql,
       const __half* __restrict__ Kvh, float* __restrict__ Sout,
       float2* __restrict__ stats)
{
    extern __shared__ char smem[];
    const int ATS  = 8192;
    const int BOFF = 4 * ATS;          // A: AH0|AL0|AH1|AL1 (32 KB)
    const int BTS  = 2 * ATS;          // one B tile (16 KB)
    const int SOFF = BOFF + 3 * BTS;   // 80 KB; stats 4 KB

    int z = blockIdx.z;
    int b = z / NHEADS, h = z - b * NHEADS;
    int row0 = blockIdx.y << 7;

    int t = threadIdx.x, warp = t >> 5, lane = t & 31;
    int wm = warp >> 2, wn = warp & 3;
    int frow = t >> 2, fc = t & 3;
    uint32_t foff = (uint32_t)frow * 64 + ((fc ^ (frow & 3)) << 4);

    const __half* qh = Qh + (long long)(b * SEQ + row0 + frow) * DMODEL + h * HDIM + fc * 8;
    const __half* ql = Ql + (long long)(b * SEQ + row0 + frow) * DMODEL + h * HDIM + fc * 8;
    const __half* kb = Kvh + (long long)(b * SEQ) * (2 * DMODEL) + h * HDIM + fc * 8;
    float* Sb = Sout + (long long)z * SEQ * SEQ;
    uint32_t sb = smem_u32(smem);

    // prologue: A + B0 -> G0 ; B1 -> G1
    cpa16(sb + 0 * ATS + foff, qh);
    cpa16(sb + 1 * ATS + foff, ql);
    cpa16(sb + 2 * ATS + foff, qh + 32);
    cpa16(sb + 3 * ATS + foff, ql + 32);
    {
        const __half* s0 = kb + (long long)frow * (2 * DMODEL);
        cpa16(sb + BOFF + foff, s0);
        cpa16(sb + BOFF + ATS + foff, s0 + 32);
    }
    CPA_COMMIT();
    {
        const __half* s1 = kb + (long long)(128 + frow) * (2 * DMODEL);
        cpa16(sb + BOFF + BTS + foff, s1);
        cpa16(sb + BOFF + BTS + ATS + foff, s1 + 32);
    }
    CPA_COMMIT();

    int arow_base = wm * 32 + (lane & 15);
    int asel      = lane >> 4;
    int nrow_base = wn * 32 + (lane & 7) + ((lane >> 4) << 3);
    int bsel      = (lane >> 3) & 1;

    float mrun[2][2], srun[2][2];
    #pragma unroll
    for (int i = 0; i < 2; i++)
        #pragma unroll
        for (int j = 0; j < 2; j++) { mrun[i][j] = -1e30f; srun[i][j] = 0.f; }

    for (int nt = 0; nt < 8; nt++) {
        cpa_wait<1>();
        __syncthreads();
        int ft = nt + 2;
        if (ft < 8) {
            const __half* s = kb + (long long)(ft * 128 + frow) * (2 * DMODEL);
            uint32_t d = sb + BOFF + (ft % 3) * BTS + foff;
            cpa16(d, s);
            cpa16(d + ATS, s + 32);
        }
        CPA_COMMIT();

        float acc[2][4][4];
        #pragma unroll
        for (int i = 0; i < 2; i++)
            #pragma unroll
            for (int j = 0; j < 4; j++)
                #pragma unroll
                for (int q = 0; q < 4; q++) acc[i][j][q] = 0.f;

        uint32_t sBb = sb + BOFF + (nt % 3) * BTS;
        #pragma unroll
        for (int kt = 0; kt < 2; kt++) {
            uint32_t sA  = sb + kt * 2 * ATS;
            uint32_t sBk = sBb + kt * ATS;
            #pragma unroll
            for (int ks = 0; ks < 2; ks++) {
                uint32_t ah[2][4], al[2][4];
                #pragma unroll
                for (int mi = 0; mi < 2; mi++) {
                    int r = arow_base + mi * 16;
                    uint32_t ch = (uint32_t)(ks * 2 + asel) ^ (r & 3);
                    uint32_t off = (uint32_t)r * 64 + (ch << 4);
                    ldsm4(sA + off, ah[mi]);
                    ldsm4(sA + ATS + off, al[mi]);
                }
                uint32_t bq[4][2];
                #pragma unroll
                for (int p = 0; p < 2; p++) {
                    int n = nrow_base + p * 16;
                    uint32_t ch = (uint32_t)(ks * 2 + bsel) ^ (n & 3);
                    uint32_t off = (uint32_t)n * 64 + (ch << 4);
                    uint32_t rh[4];
                    ldsm4(sBk + off, rh);
                    bq[2 * p][0] = rh[0]; bq[2 * p][1] = rh[1];
                    bq[2 * p + 1][0] = rh[2]; bq[2 * p + 1][1] = rh[3];
                }
                #pragma unroll
                for (int mi = 0; mi < 2; mi++)
                    #pragma unroll
                    for (int ni = 0; ni < 4; ni++) {
                        mma16816(acc[mi][ni], ah[mi], bq[ni]);
                        mma16816(acc[mi][ni], al[mi], bq[ni]);
                    }
            }
        }

        int colb = nt * 128;
        #pragma unroll
        for (int mi = 0; mi < 2; mi++) {
            #pragma unroll
            for (int ni = 0; ni < 4; ni++)
                #pragma unroll
                for (int q = 0; q < 4; q++) acc[mi][ni][q] *= 0.125f;

            int r = row0 + wm * 32 + mi * 16 + (lane >> 2);
            #pragma unroll
            for (int hq = 0; hq < 2; hq++) {
                float tm = -1e30f;
                #pragma unroll
                for (int ni = 0; ni < 4; ni++)
                    tm = fmaxf(tm, fmaxf(acc[mi][ni][2 * hq], acc[mi][ni][2 * hq + 1]));
                float nm = fmaxf(mrun[mi][hq], tm);
                float s = srun[mi][hq] * __expf(mrun[mi][hq] - nm);
                #pragma unroll
                for (int ni = 0; ni < 4; ni++)
                    s += __expf(acc[mi][ni][2 * hq] - nm) + __expf(acc[mi][ni][2 * hq + 1] - nm);
                mrun[mi][hq] = nm;
                srun[mi][hq] = s;
            }
            #pragma unroll
            for (int ni = 0; ni < 4; ni++) {
                int c = colb + wn * 32 + ni * 8 + (lane & 3) * 2;
                float* cp = Sb + (long long)r * SEQ + c;
                *(float2*)cp = make_float2(acc[mi][ni][0], acc[mi][ni][1]);
                *(float2*)(cp + 8 * SEQ) = make_float2(acc[mi][ni][2], acc[mi][ni][3]);
            }
        }
    }

    #pragma unroll
    for (int mi = 0; mi < 2; mi++)
        #pragma unroll
        for (int hq = 0; hq < 2; hq++) {
            float m = mrun[mi][hq], s = srun[mi][hq];
            #pragma unroll
            for (int o = 1; o <= 2; o <<= 1) {
                float mo = __shfl_xor_sync(0xffffffffu, m, o);
                float so = __shfl_xor_sync(0xffffffffu, s, o);
                float nm = fmaxf(m, mo);
                s = s * __expf(m - nm) + so * __expf(mo - nm);
                m = nm;
            }
            if ((lane & 3) == 0) {
                int rl = wm * 32 + mi * 16 + hq * 8 + (lane >> 2);
                *(float2*)(smem + SOFF + (rl * 4 + wn) * 8) = make_float2(m, s);
            }
        }
    __syncthreads();
    if (t < 128) {
        float2 p0 = *(float2*)(smem + SOFF + (t * 4 + 0) * 8);
        float2 p1 = *(float2*)(smem + SOFF + (t * 4 + 1) * 8);
        float2 p2 = *(float2*)(smem + SOFF + (t * 4 + 2) * 8);
        float2 p3 = *(float2*)(smem + SOFF + (t * 4 + 3) * 8);
        float m = fmaxf(fmaxf(p0.x, p1.x), fmaxf(p2.x, p3.x));
        float s = p0.y * __expf(p0.x - m) + p1.y * __expf(p1.x - m)
                + p2.y * __expf(p2.x - m) + p3.y * __expf(p3.x - m);
        stats[(long long)z * SEQ + row0 + t] = make_float2(m, s);
    }
}

// ---------------------------------------------------------------------------
// Fused normalize + AV: reads raw S, p = exp(s-m)/sum, writes attn in place,
// ctx = p @ V (B = Vt fp16 via cp.async triple buffer). ctx out as fp16 pair.
// ---------------------------------------------------------------------------
__global__ void __launch_bounds__(512)
pav_gemm(float* __restrict__ Sm, const __half* __restrict__ Vth,
         const float2* __restrict__ stats,
         __half* __restrict__ Ch, __half* __restrict__ Cl)
{
    extern __shared__ char smem[];
    const int ASTG = 16384;     // per A stage: AH 8KB + AL 8KB
    const int BOFF = 2 * ASTG;  // 32 KB
    const int BTS  = 4096;

    int z = blockIdx.z;
    int b = z / NHEADS, h = z - b * NHEADS;
    int row0 = blockIdx.y << 7;

    int t = threadIdx.x, warp = t >> 5, lane = t & 31;
    int wm = warp >> 2, wn = warp & 3;
    int frow = t >> 2, fc = t & 3;
    uint32_t foff = (uint32_t)frow * 64 + ((fc ^ (frow & 3)) << 4);

    float* Asrc = Sm + (long long)z * SEQ * SEQ + (long long)(row0 + frow) * SEQ + fc * 8;
    const bool bact = (t < 256);
    const __half* Bsrc = Vth + (long long)z * HDIM * SEQ + (long long)frow * SEQ + fc * 8;

    float2 st = stats[(long long)z * SEQ + row0 + frow];
    float mrow = st.x, inv = 1.0f / st.y;

    uint32_t sb = smem_u32(smem);

    float acc[2][2][4];
    #pragma unroll
    for (int i = 0; i < 2; i++)
        #pragma unroll
        for (int j = 0; j < 2; j++)
            #pragma unroll
            for (int q = 0; q < 4; q++) acc[i][j][q] = 0.0f;

    // prologue: B0, B1 via cp.async; A0 exp path
    if (bact) cpa16(sb + BOFF + foff, Bsrc);
    CPA_COMMIT();
    if (bact) cpa16(sb + BOFF + BTS + foff, Bsrc + 32);
    CPA_COMMIT();
    {
        float4 a0 = *(const float4*)(Asrc);
        float4 a1 = *(const float4*)(Asrc + 4);
        a0.x = __expf(a0.x - mrow) * inv; a0.y = __expf(a0.y - mrow) * inv;
        a0.z = __expf(a0.z - mrow) * inv; a0.w = __expf(a0.w - mrow) * inv;
        a1.x = __expf(a1.x - mrow) * inv; a1.y = __expf(a1.y - mrow) * inv;
        a1.z = __expf(a1.z - mrow) * inv; a1.w = __expf(a1.w - mrow) * inv;
        *(float4*)(Asrc)     = a0;
        *(float4*)(Asrc + 4) = a1;
        uint4 hv, lv;
        cvt8h(a0, a1, hv, lv);
        *(uint4*)(smem + foff)        = hv;
        *(uint4*)(smem + 8192 + foff) = lv;
    }

    int arow_base = wm * 32 + (lane & 15);
    int asel      = lane >> 4;
    int nrow_base = wn * 16 + (lane & 7) + ((lane >> 4) << 3);
    int bsel      = (lane >> 3) & 1;

    const int nk = SEQ / 32;   // 32
    for (int it = 0; it < nk; it++) {
        cpa_wait<1>();
        __syncthreads();
        bool more = (it + 1 < nk);
        float4 la0, la1;
        if (more) {
            int k0 = (it + 1) << 5;
            la0 = *(const float4*)(Asrc + k0);
            la1 = *(const float4*)(Asrc + k0 + 4);
        }
        int ft = it + 2;
        if (ft < nk && bact)
            cpa16(sb + BOFF + (ft % 3) * BTS + foff, Bsrc + ft * 32);
        CPA_COMMIT();

        uint32_t sA = sb + (it & 1) * ASTG;
        uint32_t sB = sb + BOFF + (it % 3) * BTS;

        #pragma unroll
        for (int ks = 0; ks < 2; ks++) {
            uint32_t ah[2][4], al[2][4];
            #pragma unroll
            for (int mi = 0; mi < 2; mi++) {
                int r = arow_base + mi * 16;
                uint32_t ch = (uint32_t)(ks * 2 + asel) ^ (r & 3);
                uint32_t off = (uint32_t)r * 64 + (ch << 4);
                ldsm4(sA + off, ah[mi]);
                ldsm4(sA + 8192 + off, al[mi]);
            }
            uint32_t bq[2][2];
            {
                int n = nrow_base;
                uint32_t ch = (uint32_t)(ks * 2 + bsel) ^ (n & 3);
                uint32_t off = (uint32_t)n * 64 + (ch << 4);
                uint32_t rh[4];
                ldsm4(sB + off, rh);
                bq[0][0] = rh[0]; bq[0][1] = rh[1];
                bq[1][0] = rh[2]; bq[1][1] = rh[3];
            }
            #pragma unroll
            for (int mi = 0; mi < 2; mi++)
                #pragma unroll
                for (int ni = 0; ni < 2; ni++) {
                    mma16816(acc[mi][ni], ah[mi], bq[ni]);
                    mma16816(acc[mi][ni], al[mi], bq[ni]);
                }
        }

        if (more) {
            int k0 = (it + 1) << 5;
            la0.x = __expf(la0.x - mrow) * inv; la0.y = __expf(la0.y - mrow) * inv;
            la0.z = __expf(la0.z - mrow) * inv; la0.w = __expf(la0.w - mrow) * inv;
            la1.x = __expf(la1.x - mrow) * inv; la1.y = __expf(la1.y - mrow) * inv;
            la1.z = __expf(la1.z - mrow) * inv; la1.w = __expf(la1.w - mrow) * inv;
            *(float4*)(Asrc + k0)     = la0;
            *(float4*)(Asrc + k0 + 4) = la1;
            char* stg = smem + ((it + 1) & 1) * ASTG;
            uint4 hv, lv;
            cvt8h(la0, la1, hv, lv);
            *(uint4*)(stg + foff)        = hv;
            *(uint4*)(stg + 8192 + foff) = lv;
        }
    }

    // epilogue -> ctx_h/ctx_l [b, row, h*64 + c]
    __half* Cbh = Ch + (long long)(b * SEQ) * DMODEL + h * HDIM;
    __half* Cbl = Cl + (long long)(b * SEQ) * DMODEL + h * HDIM;
    #pragma unroll
    for (int mi = 0; mi < 2; mi++) {
        int r = row0 + wm * 32 + mi * 16 + (lane >> 2);
        #pragma unroll
        for (int ni = 0; ni < 2; ni++) {
            int cidx = wn * 16 + ni * 8 + (lane & 3) * 2;
            float v0 = acc[mi][ni][0], v1 = acc[mi][ni][1];
            float v2 = acc[mi][ni][2], v3 = acc[mi][ni][3];
            uint32_t h0 = packh2(v0, v1), h1 = packh2(v2, v3);
            *(uint32_t*)(Cbh + (long long)r * DMODEL + cidx) = h0;
            *(uint32_t*)(Cbh + (long long)(r + 8) * DMODEL + cidx) = h1;
            __half2 H0 = *(__half2*)&h0, H1 = *(__half2*)&h1;
            *(uint32_t*)(Cbl + (long long)r * DMODEL + cidx) =
                packh2(v0 - __low2float(H0), v1 - __high2float(H0));
            *(uint32_t*)(Cbl + (long long)(r + 8) * DMODEL + cidx) =
                packh2(v2 - __low2float(H1), v3 - __high2float(H1));
        }
    }
}

// ---------------------------------------------------------------------------
// Transpose V half of kv_h into vt_h[(b*12+h)*64 + d][tok]
// ---------------------------------------------------------------------------
__global__ void __launch_bounds__(256)
transpose_vh(const __half* __restrict__ kvh, __half* __restrict__ vth)
{
    __shared__ float s[64][65];
    int bh = blockIdx.x;
    int b = bh / NHEADS, h = bh - b * NHEADS;
    int tk = blockIdx.y << 6;
    int t = threadIdx.x;
    int tl = t >> 2;
    int ds = (t & 3) << 4;

    const __half* src = kvh + (long long)(b * SEQ + tk + tl) * (2 * DMODEL)
                            + DMODEL + h * HDIM + ds;
    uint4 u0 = *(const uint4*)(src);
    uint4 u1 = *(const uint4*)(src + 8);
    #pragma unroll
    for (int j = 0; j < 4; j++) {
        __half2 p = ((__half2*)&u0)[j];
        s[tl][ds + 2 * j]     = __low2float(p);
        s[tl][ds + 2 * j + 1] = __high2float(p);
        __half2 q = ((__half2*)&u1)[j];
        s[tl][ds + 8 + 2 * j]     = __low2float(q);
        s[tl][ds + 8 + 2 * j + 1] = __high2float(q);
    }
    __syncthreads();

    int dl = t >> 2;
    int ts = (t & 3) << 4;
    uint32_t w[8];
    #pragma unroll
    for (int j = 0; j < 8; j++)
        w[j] = packh2(s[ts + 2 * j][dl], s[ts + 2 * j + 1][dl]);
    __half* dst = vth + (long long)(bh * HDIM + dl) * SEQ + tk + ts;
    *(uint4*)dst       = make_uint4(w[0], w[1], w[2], w[3]);
    *(uint4*)(dst + 8) = make_uint4(w[4], w[5], w[6], w[7]);
}

// ---------------------------------------------------------------------------
// d_in: 0=x [8,1024,768] f32, 1=q_w, 2=kv_w, 3=proj_w, 4=proj_b, 5=H, 6=W
// d_out: out [8*1024*768] f32 followed by attn [8*12*1024*1024] f32
// ---------------------------------------------------------------------------
extern "C" void kernel_launch(void* const* d_in, const int* in_sizes, int n_in,
                              void* d_out, int out_size)
{
    const float* x   = (const float*)d_in[0];
    const float* qw  = (const float*)d_in[1];
    const float* kvw = (const float*)d_in[2];
    const float* pw  = (const float*)d_in[3];
    const float* pb  = (const float*)d_in[4];

    float* out  = (float*)d_out;
    float* attn = out + (long long)B_ * SEQ * DMODEL;

    __half *xh, *xl, *qwh, *kvwh, *pwh, *qh, *ql, *kvh, *vth, *ctxh, *ctxl;
    float2* gst;
    cudaGetSymbolAddress((void**)&xh,   g_xh);
    cudaGetSymbolAddress((void**)&xl,   g_xl);
    cudaGetSymbolAddress((void**)&qwh,  g_qwh);
    cudaGetSymbolAddress((void**)&kvwh, g_kvwh);
    cudaGetSymbolAddress((void**)&pwh,  g_pwh);
    cudaGetSymbolAddress((void**)&qh,   g_qh);
    cudaGetSymbolAddress((void**)&ql,   g_ql);
    cudaGetSymbolAddress((void**)&kvh,  g_kvh);
    cudaGetSymbolAddress((void**)&vth,  g_vth);
    cudaGetSymbolAddress((void**)&ctxh, g_ctxh);
    cudaGetSymbolAddress((void**)&ctxl, g_ctxl);
    cudaGetSymbolAddress((void**)&gst,  g_st);

    const int SMEM_PROJ = 4 * 3 * 8192;            // 98304
    const int SMEM_S    = 4 * 8192 + 3 * 16384 + 4096;  // 86016
    const int SMEM_PAV  = 2 * 16384 + 3 * 4096;    // 45056
    cudaFuncSetAttribute(proj_f16, cudaFuncAttributeMaxDynamicSharedMemorySize, SMEM_PROJ);
    cudaFuncSetAttribute(s_gemm,   cudaFuncAttributeMaxDynamicSharedMemorySize, SMEM_S);
    cudaFuncSetAttribute(pav_gemm, cudaFuncAttributeMaxDynamicSharedMemorySize, SMEM_PAV);

    // 0) operand conversions
    {
        int n8x = B_ * SEQ * DMODEL / 8;           // 786432
        cvt_split<<<(n8x + 255) / 256, 256>>>(x, xh, xl, n8x);
        int n8q = DMODEL * DMODEL / 8;             // 73728
        cvt_split<<<(n8q + 255) / 256, 256>>>(qw, qwh, nullptr, n8q);
        int n8k = 2 * DMODEL * DMODEL / 8;
        cvt_split<<<(n8k + 255) / 256, 256>>>(kvw, kvwh, nullptr, n8k);
        cvt_split<<<(n8q + 255) / 256, 256>>>(pw, pwh, nullptr, n8q);
    }

    const int MROWS = B_ * SEQ;                    // 8192

    // 1) Q = x @ q_w^T  -> fp16 pair
    proj_f16<<<dim3(DMODEL / 128, MROWS / 128, 1), 512, SMEM_PROJ>>>(
        xh, xl, qwh, nullptr, nullptr, qh, ql,
        DMODEL, DMODEL, DMODEL, DMODEL);

    // 2) KV = x @ kv_w^T -> fp16 hi
    proj_f16<<<dim3(2 * DMODEL / 128, MROWS / 128, 1), 512, SMEM_PROJ>>>(
        xh, xl, kvwh, nullptr, nullptr, kvh, nullptr,
        DMODEL, DMODEL, DMODEL, 2 * DMODEL);

    // 2b) V^T per (b,h)
    transpose_vh<<<dim3(BH_, SEQ / 64, 1), 256>>>(kvh, vth);

    // 3) S = 0.125 * Q @ K^T  (+ per-row softmax stats)
    s_gemm<<<dim3(1, SEQ / 128, BH_), 512, SMEM_S>>>(qh, ql, kvh, attn, gst);

    // 4) fused: attn = softmax(S) in place, ctx = attn @ V -> fp16 pair
    pav_gemm<<<dim3(1, SEQ / 128, BH_), 512, SMEM_PAV>>>(attn, vth, gst, ctxh, ctxl);

    // 5) out = ctx @ proj_w^T + proj_b
    proj_f16<<<dim3(DMODEL / 128, MROWS / 128, 1), 512, SMEM_PROJ>>>(
        ctxh, ctxl, pwh, out, pb, nullptr, nullptr,
        DMODEL, DMODEL, DMODEL, DMODEL);
}